// round 15
// baseline (speedup 1.0000x reference)
#include <cuda_runtime.h>
#include <cuda_bf16.h>
#include <cuda_fp16.h>
#include <math.h>
#include <stdint.h>

// Problem constants (fixed shapes)
#define BB 4
#define NN 1024
#define EE 16
#define SS 4
#define HH 64          // AH == PH == 64
#define NT 32          // tiles per dimension (N/32)
#define NTRI 528       // triangular 32x32 tiles per batch
#define NTASKS (BB * NTRI * 32)      // 67584 warp-tasks (one i-row x 32 j)

#define MAX_CTAS 768
#define MAXW 3072                    // warp partial slots (>= MAX_CTAS*4)

#define STRIDE_B 144                 // 72 fp16 per row: conflict-free ldmatrix
#define TC_STRIDE 66                 // even stride -> aligned float2/u64
#define LO_SCALE 1024.0f
#define LO_INV   (1.0f / 1024.0f)

typedef unsigned long long u64;

// ---------------- device scratch (no allocations allowed) ----------------
__device__ float g_cp[BB * NN * 2];
__device__ float g_Tatom[SS * HH];
__device__ float g_Tpi[SS * HH];
__device__ float g_Tpj[SS * HH];
__device__ float g_ACbase[BB * HH];
__device__ float g_Pbase[BB * HH];
__device__ float g_pairW[BB * MAXW];   // zero-init; unlaunched slots stay 0
__device__ float g_atomPart[BB * 4];

// ---------------- small helpers ----------------
__device__ __forceinline__ u64 pk2(float a, float b) {
    u64 r; asm("mov.b64 %0, {%1, %2};" : "=l"(r) : "f"(a), "f"(b)); return r;
}
__device__ __forceinline__ u64 fma2(u64 a, u64 b, u64 c) {
    u64 d; asm("fma.rn.f32x2 %0, %1, %2, %3;" : "=l"(d) : "l"(a), "l"(b), "l"(c)); return d;
}
__device__ __forceinline__ void upk2(u64 v, float& x, float& y) {
    asm("mov.b64 {%0, %1}, %2;" : "=f"(x), "=f"(y) : "l"(v));
}
// exact-ish silu (atom channel)
__device__ __forceinline__ float silu_f(float x) {
    const float t = __expf(-x);
    return __fdividef(x, 1.0f + t);
}
// fast silu via tanh.approx: silu(x) = hx + hx*tanh(hx), hx = x/2
__device__ __forceinline__ float silu_t(float x) {
    const float hx = 0.5f * x;
    float t;
    asm("tanh.approx.f32 %0, %1;" : "=f"(t) : "f"(hx));
    return fmaf(hx, t, hx);
}
__device__ __forceinline__ uint32_t smem_u32(const void* p) {
    uint32_t a;
    asm("{ .reg .u64 tmp; cvta.to.shared.u64 tmp, %1; cvt.u32.u64 %0, tmp; }"
        : "=r"(a) : "l"(p));
    return a;
}
// fp16x2 pack: word = {hi = odd-k value, lo = even-k value}
__device__ __forceinline__ uint32_t packh2(float odd, float even) {
    uint32_t w;
    asm("cvt.rn.f16x2.f32 %0, %1, %2;" : "=r"(w) : "f"(odd), "f"(even));
    return w;
}
__device__ __forceinline__ void ldsm2(uint32_t* r, uint32_t addr) {
    asm volatile("ldmatrix.sync.aligned.m8n8.x2.shared.b16 {%0,%1}, [%2];"
                 : "=r"(r[0]), "=r"(r[1]) : "r"(addr));
}
__device__ __forceinline__ void mma_f16s(float* c, const uint32_t* a,
                                         uint32_t b0, uint32_t b1) {
    asm volatile(
        "mma.sync.aligned.m16n8k16.row.col.f32.f16.f16.f32 "
        "{%0,%1,%2,%3}, {%4,%5,%6,%7}, {%8,%9}, {%0,%1,%2,%3};"
        : "+f"(c[0]), "+f"(c[1]), "+f"(c[2]), "+f"(c[3])
        : "r"(a[0]), "r"(a[1]), "r"(a[2]), "r"(a[3]), "r"(b0), "r"(b1));
}

// ---------------- prep: means, cp, tables (parallel over batches) ----------------
__global__ void prep_kernel(const float* __restrict__ pos,
                            const float* __restrict__ ef,
                            const float* __restrict__ embed,
                            const float* __restrict__ aW0,
                            const float* __restrict__ ab0,
                            const float* __restrict__ pW0,
                            const float* __restrict__ pb0) {
    const int tid = threadIdx.x; // 256 threads
    const int b = blockIdx.x;    // one block per batch
    __shared__ float sx_[256], sy_[256];

    float sx = 0.f, sy = 0.f;
    for (int n = tid; n < NN; n += 256) {
        sx += pos[(b * NN + n) * 2 + 0];
        sy += pos[(b * NN + n) * 2 + 1];
    }
    sx_[tid] = sx; sy_[tid] = sy;
    __syncthreads();
    for (int s = 128; s > 0; s >>= 1) {
        if (tid < s) { sx_[tid] += sx_[tid + s]; sy_[tid] += sy_[tid + s]; }
        __syncthreads();
    }
    const float mx = sx_[0] * (1.f / NN);
    const float my = sy_[0] * (1.f / NN);
    for (int n = tid; n < NN; n += 256) {
        g_cp[(b * NN + n) * 2 + 0] = pos[(b * NN + n) * 2 + 0] - mx;
        g_cp[(b * NN + n) * 2 + 1] = pos[(b * NN + n) * 2 + 1] - my;
    }

    if (b == 0) {   // species tables: 256 entries, one per thread
        const int s = tid >> 6, k = tid & 63;
        float ta = 0.f, tpi = 0.f, tpj = 0.f;
#pragma unroll
        for (int e = 0; e < EE; e++) {
            const float em = embed[s * EE + e];
            ta  += em * aW0[(5 + e) * HH + k];
            tpi += em * pW0[(5 + e) * HH + k];
            tpj += em * pW0[(21 + e) * HH + k];
        }
        g_Tatom[tid] = ta; g_Tpi[tid] = tpi; g_Tpj[tid] = tpj;
    }
    if (tid < HH) {
        const int k = tid;
        const float Ex = ef[b * 2], Ey = ef[b * 2 + 1];
        const float en = sqrtf(Ex * Ex + Ey * Ey);
        g_ACbase[b * HH + k] = Ex * aW0[2 * HH + k] + Ey * aW0[3 * HH + k]
                             + en * aW0[4 * HH + k] + ab0[k];
        g_Pbase[b * HH + k]  = en * pW0[4 * HH + k] + pb0[k];
    }
}

// ---------------- atom channel (tiny; known-good f32x2 version) ----------------
__global__ __launch_bounds__(256, 2)
void atom_kernel(const int* __restrict__ species,
                 const float* __restrict__ aW0,
                 const float* __restrict__ aW1,
                 const float* __restrict__ ab1,
                 const float* __restrict__ aW2,
                 const float* __restrict__ ab2) {
    __shared__ __align__(16) float sW1[HH * HH];
    __shared__ float sTA[SS * 65];
    __shared__ float2 sGeo[HH];
    __shared__ __align__(16) float sB1[HH];
    __shared__ float sW2[HH];
    __shared__ float sRed[256];

    const int tid = threadIdx.x;
    const int b = blockIdx.y;
    const int n = blockIdx.x * 256 + tid;

    for (int idx = tid; idx < HH * HH; idx += 256) sW1[idx] = aW1[idx];
    for (int idx = tid; idx < SS * HH; idx += 256) {
        const int s = idx >> 6, k = idx & 63;
        sTA[s * 65 + k] = g_ACbase[b * HH + k] + g_Tatom[s * HH + k];
    }
    if (tid < HH) {
        sGeo[tid] = make_float2(aW0[tid], aW0[HH + tid]);
        sB1[tid] = ab1[tid];
        sW2[tid] = aW2[tid];
    }
    __syncthreads();

    const float cx = g_cp[(b * NN + n) * 2 + 0];
    const float cy = g_cp[(b * NN + n) * 2 + 1];
    const int sp = species[b * NN + n];
    const float* ta = &sTA[sp * 65];

    float h0[HH];
#pragma unroll
    for (int k = 0; k < HH; k++) {
        const float2 g = sGeo[k];
        const float z = fmaf(cx, g.x, fmaf(cy, g.y, ta[k]));
        h0[k] = silu_f(z);
    }

    float e = ab2[0];
#pragma unroll
    for (int kc = 0; kc < HH; kc += 32) {
        u64 acc[16];
        const u64* b1p = (const u64*)&sB1[kc];
#pragma unroll
        for (int m = 0; m < 16; m++) acc[m] = b1p[m];
#pragma unroll
        for (int j = 0; j < HH; j++) {
            const u64 hj = pk2(h0[j], h0[j]);
            const ulonglong2* w = (const ulonglong2*)&sW1[j * HH + kc];
#pragma unroll
            for (int m = 0; m < 8; m++) {
                const ulonglong2 ww = w[m];
                acc[2 * m + 0] = fma2(hj, ww.x, acc[2 * m + 0]);
                acc[2 * m + 1] = fma2(hj, ww.y, acc[2 * m + 1]);
            }
        }
#pragma unroll
        for (int m = 0; m < 16; m++) {
            float z0, z1;
            upk2(acc[m], z0, z1);
            e = fmaf(silu_f(z0), sW2[kc + 2 * m + 0], e);
            e = fmaf(silu_f(z1), sW2[kc + 2 * m + 1], e);
        }
    }

    sRed[tid] = e;
    __syncthreads();
    for (int s = 128; s > 0; s >>= 1) {
        if (tid < s) sRed[tid] += sRed[tid + s];
        __syncthreads();
    }
    if (tid == 0) g_atomPart[b * 4 + blockIdx.x] = sRed[0];
}

// ---------------- pair channel: persistent warp-task HMMA ----------------
// fp16 2-term B: Bhi = fp16(W1^T), Blo = fp16(1024*(W1^T - Bhi)) with a
// separate accumulator merged by *2^-10. Systematic weight error ~5e-7.
// A is single fp16 (random per-pair rounding; averages out over pairs).
__global__ __launch_bounds__(128, 5)
void pair_mma_kernel(const int* __restrict__ species,
                     const float* __restrict__ ef,
                     const float* __restrict__ pW0,
                     const float* __restrict__ pW1,
                     const float* __restrict__ pb1,
                     const float* __restrict__ pW2,
                     const float* __restrict__ pb2) {
    __shared__ __align__(16) char sBh[HH * STRIDE_B];     // W1^T fp16 hi
    __shared__ __align__(16) char sBl[HH * STRIDE_B];     // residual * 1024, fp16
    __shared__ __align__(16) float sTcomb[BB * 16 * TC_STRIDE];
    __shared__ __align__(16) u64 sGx[32], sGy[32], sGz[32], sGw[32];
    __shared__ __align__(8) float sB1[HH];
    __shared__ __align__(8) float sW2[HH];
    __shared__ float2 sEF[BB];

    const int tid  = threadIdx.x;
    const int wid  = tid >> 5;
    const int lane = tid & 31;

    // ---- init: B = W1^T (rows n, cols k=j)
    for (int idx = tid; idx < HH * HH; idx += 128) {
        const int n = idx >> 6, j = idx & 63;
        const float w = pW1[j * HH + n];
        const __half wh = __float2half_rn(w);
        const float r = (w - __half2float(wh)) * LO_SCALE;
        *(__half*)(sBh + n * STRIDE_B + j * 2) = wh;
        *(__half*)(sBl + n * STRIDE_B + j * 2) = __float2half_rn(r);
    }
    for (int idx = tid; idx < BB * 16 * HH; idx += 128) {
        const int bc = idx >> 6, k = idx & 63;
        const int b = bc >> 4, c = bc & 15;
        sTcomb[bc * TC_STRIDE + k] = g_Pbase[b * HH + k]
                                   + g_Tpi[(c >> 2) * HH + k]
                                   + g_Tpj[(c & 3) * HH + k];
    }
    if (tid < 32) {   // pair-packed geometry tables
        const int k = tid * 2;
        sGx[tid] = pk2(pW0[0 * HH + k], pW0[0 * HH + k + 1]);
        sGy[tid] = pk2(pW0[1 * HH + k], pW0[1 * HH + k + 1]);
        sGz[tid] = pk2(pW0[2 * HH + k], pW0[2 * HH + k + 1]);
        sGw[tid] = pk2(pW0[3 * HH + k], pW0[3 * HH + k + 1]);
    }
    if (tid < HH) {
        sB1[tid] = pb1[tid];
        sW2[tid] = pW2[tid];
    }
    if (tid < BB) sEF[tid] = make_float2(ef[tid * 2], ef[tid * 2 + 1]);
    __syncthreads();

    // ldsm2 address pieces: row = (lane&7), k-half = ((lane>>3)&1)*16 bytes
    const uint32_t bh_u = smem_u32(sBh) + (lane & 7) * STRIDE_B + ((lane >> 3) & 1) * 16;
    const uint32_t bl_u = smem_u32(sBl) + (lane & 7) * STRIDE_B + ((lane >> 3) & 1) * 16;
    const int kc4 = (lane & 3) * 2;        // fragment k offset within 16-k step
    const float pb2v = pb2[0];

    float bacc[BB];
#pragma unroll
    for (int b = 0; b < BB; b++) bacc[b] = 0.f;

    const int nwarps = gridDim.x * 4;
    const int gw = blockIdx.x * 4 + wid;

    for (int task = gw; task < NTASKS; task += nwarps) {
        // decode: b, tri -> (ti, tj), il
        const int b = task / (NTRI * 32);
        const int tt = task - b * (NTRI * 32);
        const int tri = tt >> 5, il = tt & 31;
        int rem = tri, ti = 0;
        while (rem >= NT - ti) { rem -= (NT - ti); ti++; }
        const int tj = ti + rem;
        if (ti == tj && il == 31) continue;   // fully-masked row

        const int gi = ti * NT + il;
        const float2 ci = *(const float2*)&g_cp[(b * NN + gi) * 2];
        const int si = species[b * NN + gi];
        const float2 EF = sEF[b];

        // ---- A fragments for ALL 4 K-steps, computed up front (32 regs)
        uint32_t ahi[4][2][4];
        {
            u64 rx2[4], ry2[4], dd2[4], ee2[4];
            int tcoff[4];
#pragma unroll
            for (int m = 0; m < 4; m++) {
                const int gj = tj * NT + (lane >> 2) + 8 * m;
                const float2 cj = *(const float2*)&g_cp[(b * NN + gj) * 2];
                const int sj = species[b * NN + gj];
                const float x = ci.x - cj.x, y = ci.y - cj.y;
                const float d = sqrtf(x * x + y * y);
                const float dm = fmaxf(d, 1e-12f);
                const float edu = __fdividef(fmaf(EF.x, x, EF.y * y), dm);
                rx2[m] = pk2(x, x); ry2[m] = pk2(y, y);
                dd2[m] = pk2(d, d); ee2[m] = pk2(edu, edu);
                tcoff[m] = (b * 16 + si * 4 + sj) * TC_STRIDE;
            }
#pragma unroll
            for (int ks = 0; ks < 4; ks++) {
                const int p0 = ks * 8 + (lane & 3);
                const u64 gx0 = sGx[p0],     gy0 = sGy[p0];
                const u64 gz0 = sGz[p0],     gw0 = sGw[p0];
                const u64 gx1 = sGx[p0 + 4], gy1 = sGy[p0 + 4];
                const u64 gz1 = sGz[p0 + 4], gw1 = sGw[p0 + 4];
                const int kb = ks * 16 + kc4;
#pragma unroll
                for (int m = 0; m < 4; m++) {
                    const float* tc = &sTcomb[tcoff[m]];
                    u64 z01 = *(const u64*)(tc + kb);
                    z01 = fma2(rx2[m], gx0, z01); z01 = fma2(ry2[m], gy0, z01);
                    z01 = fma2(dd2[m], gz0, z01); z01 = fma2(ee2[m], gw0, z01);
                    u64 z89 = *(const u64*)(tc + kb + 8);
                    z89 = fma2(rx2[m], gx1, z89); z89 = fma2(ry2[m], gy1, z89);
                    z89 = fma2(dd2[m], gz1, z89); z89 = fma2(ee2[m], gw1, z89);
                    float z0, z1, z8, z9;
                    upk2(z01, z0, z1); upk2(z89, z8, z9);
                    const int mt = m >> 1, sl = m & 1;
                    ahi[ks][mt][0 + sl] = packh2(silu_t(z1), silu_t(z0));
                    ahi[ks][mt][2 + sl] = packh2(silu_t(z9), silu_t(z8));
                }
            }
        }

        // ---- n-loop: 8 columns per step, transient accumulators + epilogue
        float s[4] = {0.f, 0.f, 0.f, 0.f};
#pragma unroll
        for (int ns = 0; ns < 8; ns++) {
            const float2 b1 = *(const float2*)&sB1[ns * 8 + kc4];
            float aH[2][4], aL[2][4];
#pragma unroll
            for (int mt = 0; mt < 2; mt++) {
                aH[mt][0] = b1.x; aH[mt][1] = b1.y;
                aH[mt][2] = b1.x; aH[mt][3] = b1.y;
                aL[mt][0] = 0.f; aL[mt][1] = 0.f;
                aL[mt][2] = 0.f; aL[mt][3] = 0.f;
            }
#pragma unroll
            for (int ks = 0; ks < 4; ks++) {
                const uint32_t off = ns * 8 * STRIDE_B + ks * 32;
                uint32_t rh[2], rl[2];
                ldsm2(rh, bh_u + off);
                ldsm2(rl, bl_u + off);
#pragma unroll
                for (int mt = 0; mt < 2; mt++) {
                    mma_f16s(aH[mt], ahi[ks][mt], rh[0], rh[1]);
                    mma_f16s(aL[mt], ahi[ks][mt], rl[0], rl[1]);
                }
            }
            const float2 w2 = *(const float2*)&sW2[ns * 8 + kc4];
#pragma unroll
            for (int mt = 0; mt < 2; mt++) {
                const float z0 = fmaf(aL[mt][0], LO_INV, aH[mt][0]);
                const float z1 = fmaf(aL[mt][1], LO_INV, aH[mt][1]);
                const float z2 = fmaf(aL[mt][2], LO_INV, aH[mt][2]);
                const float z3 = fmaf(aL[mt][3], LO_INV, aH[mt][3]);
                s[mt * 2 + 0] = fmaf(silu_t(z0), w2.x, s[mt * 2 + 0]);
                s[mt * 2 + 0] = fmaf(silu_t(z1), w2.y, s[mt * 2 + 0]);
                s[mt * 2 + 1] = fmaf(silu_t(z2), w2.x, s[mt * 2 + 1]);
                s[mt * 2 + 1] = fmaf(silu_t(z3), w2.y, s[mt * 2 + 1]);
            }
        }

        // ---- mask + reduce
        float v = 0.f;
        int cnt = 0;
#pragma unroll
        for (int m = 0; m < 4; m++) {
            const bool mk = gi < (tj * NT + (lane >> 2) + 8 * m);
            v += mk ? s[m] : 0.f;
            cnt += (int)mk;
        }
        v += __shfl_xor_sync(0xFFFFFFFFu, v, 1);
        v += __shfl_xor_sync(0xFFFFFFFFu, v, 2);
        v = ((lane & 3) == 0) ? fmaf(pb2v, (float)cnt, v) : 0.f;
        v += __shfl_xor_sync(0xFFFFFFFFu, v, 4);
        v += __shfl_xor_sync(0xFFFFFFFFu, v, 8);
        v += __shfl_xor_sync(0xFFFFFFFFu, v, 16);
        if (lane == 0) bacc[b] += v;
    }

    if (lane == 0) {
#pragma unroll
        for (int b = 0; b < BB; b++) g_pairW[b * MAXW + gw] = bacc[b];
    }
}

// ---------------- deterministic parallel finalize ----------------
__global__ void finalize_kernel(float* __restrict__ out) {
    __shared__ float red[1024];
    const int tid = threadIdx.x;
    const int b = tid >> 8, lane = tid & 255;
    float s = 0.f;
    for (int i = lane; i < MAXW; i += 256) s += g_pairW[b * MAXW + i];
    if (lane < 4) s += g_atomPart[b * 4 + lane];
    red[tid] = s;
    __syncthreads();
    for (int st = 128; st > 0; st >>= 1) {
        if (lane < st) red[tid] += red[tid + st];
        __syncthreads();
    }
    if (lane == 0) out[b] = red[tid];
}

// ---------------- launch ----------------
extern "C" void kernel_launch(void* const* d_in, const int* in_sizes, int n_in,
                              void* d_out, int out_size) {
    const float* positions = (const float*)d_in[0];
    const int*   species   = (const int*)d_in[1];
    const float* efield    = (const float*)d_in[2];
    const float* embed     = (const float*)d_in[3];
    const float* aW0 = (const float*)d_in[4];
    const float* ab0 = (const float*)d_in[5];
    const float* aW1 = (const float*)d_in[6];
    const float* ab1 = (const float*)d_in[7];
    const float* aW2 = (const float*)d_in[8];
    const float* ab2 = (const float*)d_in[9];
    const float* pW0 = (const float*)d_in[10];
    const float* pb0 = (const float*)d_in[11];
    const float* pW1 = (const float*)d_in[12];
    const float* pb1 = (const float*)d_in[13];
    const float* pW2 = (const float*)d_in[14];
    const float* pb2 = (const float*)d_in[15];
    float* out = (float*)d_out;

    int sms = 148;
    cudaDeviceGetAttribute(&sms, cudaDevAttrMultiProcessorCount, 0);
    int grid_pair = 5 * sms;
    if (grid_pair > MAX_CTAS) grid_pair = MAX_CTAS;

    prep_kernel<<<BB, 256>>>(positions, efield, embed, aW0, ab0, pW0, pb0);
    atom_kernel<<<dim3(4, BB), 256>>>(species, aW0, aW1, ab1, aW2, ab2);
    pair_mma_kernel<<<grid_pair, 128>>>(species, efield, pW0, pW1, pb1, pW2, pb2);
    finalize_kernel<<<1, 1024>>>(out);
}

// round 16
// speedup vs baseline: 1.0146x; 1.0146x over previous
#include <cuda_runtime.h>
#include <cuda_bf16.h>
#include <cuda_fp16.h>
#include <math.h>
#include <stdint.h>

// Problem constants (fixed shapes)
#define BB 4
#define NN 1024
#define EE 16
#define SS 4
#define HH 64          // AH == PH == 64
#define NT 32          // tiles per dimension (N/32)
#define NTRI 528       // triangular 32x32 tiles per batch
#define NTASKS (BB * NTRI * 32)      // 67584 warp-tasks (one i-row x 32 j)

#define MAX_CTAS 768
#define MAXW 3072                    // warp partial slots (>= MAX_CTAS*4)

#define STRIDE_B 144                 // 72 fp16 per row: conflict-free ldmatrix
#define TC_STRIDE 66                 // even stride -> aligned float2/u64
#define LO_SCALE 1024.0f
#define LO_INV   (1.0f / 1024.0f)

typedef unsigned long long u64;

// ---------------- device scratch (no allocations allowed) ----------------
__device__ float g_cp[BB * NN * 2];
__device__ float g_Tatom[SS * HH];
__device__ float g_Tpi[SS * HH];
__device__ float g_Tpj[SS * HH];
__device__ float g_ACbase[BB * HH];
__device__ float g_Pbase[BB * HH];
__device__ float g_pairW[BB * MAXW];   // zero-init; unlaunched slots stay 0
__device__ float g_atomPart[BB * 4];

// ---------------- small helpers ----------------
__device__ __forceinline__ u64 pk2(float a, float b) {
    u64 r; asm("mov.b64 %0, {%1, %2};" : "=l"(r) : "f"(a), "f"(b)); return r;
}
__device__ __forceinline__ u64 fma2(u64 a, u64 b, u64 c) {
    u64 d; asm("fma.rn.f32x2 %0, %1, %2, %3;" : "=l"(d) : "l"(a), "l"(b), "l"(c)); return d;
}
__device__ __forceinline__ void upk2(u64 v, float& x, float& y) {
    asm("mov.b64 {%0, %1}, %2;" : "=f"(x), "=f"(y) : "l"(v));
}
// exact-ish silu (atom channel)
__device__ __forceinline__ float silu_f(float x) {
    const float t = __expf(-x);
    return __fdividef(x, 1.0f + t);
}
__device__ __forceinline__ uint32_t smem_u32(const void* p) {
    uint32_t a;
    asm("{ .reg .u64 tmp; cvta.to.shared.u64 tmp, %1; cvt.u32.u64 %0, tmp; }"
        : "=r"(a) : "l"(p));
    return a;
}
// fp16x2 pack: word = {hi = first arg, lo = second arg}
__device__ __forceinline__ uint32_t packh2(float hi, float lo) {
    uint32_t w;
    asm("cvt.rn.f16x2.f32 %0, %1, %2;" : "=r"(w) : "f"(hi), "f"(lo));
    return w;
}
// packed silu on two f16 values: silu(x) = hx + hx*tanh(hx), hx = x/2
__device__ __forceinline__ uint32_t silu_h2(uint32_t z2) {
    uint32_t hx, t, r;
    asm("mul.rn.f16x2 %0, %1, %2;" : "=r"(hx) : "r"(z2), "r"(0x38003800u)); // x*0.5
    asm("tanh.approx.f16x2 %0, %1;" : "=r"(t) : "r"(hx));
    asm("fma.rn.f16x2 %0, %1, %2, %3;" : "=r"(r) : "r"(hx), "r"(t), "r"(hx));
    return r;
}
__device__ __forceinline__ void unpkh2(uint32_t w, float& lo, float& hi) {
    asm("{ .reg .b16 l, h;\n\t"
        "mov.b32 {l, h}, %2;\n\t"
        "cvt.f32.f16 %0, l;\n\t"
        "cvt.f32.f16 %1, h; }"
        : "=f"(lo), "=f"(hi) : "r"(w));
}
__device__ __forceinline__ void ldsm2(uint32_t* r, uint32_t addr) {
    asm volatile("ldmatrix.sync.aligned.m8n8.x2.shared.b16 {%0,%1}, [%2];"
                 : "=r"(r[0]), "=r"(r[1]) : "r"(addr));
}
__device__ __forceinline__ void mma_f16s(float* c, const uint32_t* a,
                                         uint32_t b0, uint32_t b1) {
    asm volatile(
        "mma.sync.aligned.m16n8k16.row.col.f32.f16.f16.f32 "
        "{%0,%1,%2,%3}, {%4,%5,%6,%7}, {%8,%9}, {%0,%1,%2,%3};"
        : "+f"(c[0]), "+f"(c[1]), "+f"(c[2]), "+f"(c[3])
        : "r"(a[0]), "r"(a[1]), "r"(a[2]), "r"(a[3]), "r"(b0), "r"(b1));
}

// ---------------- prep: means, cp, tables (parallel over batches) ----------------
__global__ void prep_kernel(const float* __restrict__ pos,
                            const float* __restrict__ ef,
                            const float* __restrict__ embed,
                            const float* __restrict__ aW0,
                            const float* __restrict__ ab0,
                            const float* __restrict__ pW0,
                            const float* __restrict__ pb0) {
    const int tid = threadIdx.x; // 256 threads
    const int b = blockIdx.x;    // one block per batch
    __shared__ float sx_[256], sy_[256];

    float sx = 0.f, sy = 0.f;
    for (int n = tid; n < NN; n += 256) {
        sx += pos[(b * NN + n) * 2 + 0];
        sy += pos[(b * NN + n) * 2 + 1];
    }
    sx_[tid] = sx; sy_[tid] = sy;
    __syncthreads();
    for (int s = 128; s > 0; s >>= 1) {
        if (tid < s) { sx_[tid] += sx_[tid + s]; sy_[tid] += sy_[tid + s]; }
        __syncthreads();
    }
    const float mx = sx_[0] * (1.f / NN);
    const float my = sy_[0] * (1.f / NN);
    for (int n = tid; n < NN; n += 256) {
        g_cp[(b * NN + n) * 2 + 0] = pos[(b * NN + n) * 2 + 0] - mx;
        g_cp[(b * NN + n) * 2 + 1] = pos[(b * NN + n) * 2 + 1] - my;
    }

    if (b == 0) {   // species tables: 256 entries, one per thread
        const int s = tid >> 6, k = tid & 63;
        float ta = 0.f, tpi = 0.f, tpj = 0.f;
#pragma unroll
        for (int e = 0; e < EE; e++) {
            const float em = embed[s * EE + e];
            ta  += em * aW0[(5 + e) * HH + k];
            tpi += em * pW0[(5 + e) * HH + k];
            tpj += em * pW0[(21 + e) * HH + k];
        }
        g_Tatom[tid] = ta; g_Tpi[tid] = tpi; g_Tpj[tid] = tpj;
    }
    if (tid < HH) {
        const int k = tid;
        const float Ex = ef[b * 2], Ey = ef[b * 2 + 1];
        const float en = sqrtf(Ex * Ex + Ey * Ey);
        g_ACbase[b * HH + k] = Ex * aW0[2 * HH + k] + Ey * aW0[3 * HH + k]
                             + en * aW0[4 * HH + k] + ab0[k];
        g_Pbase[b * HH + k]  = en * pW0[4 * HH + k] + pb0[k];
    }
}

// ---------------- atom channel (tiny; known-good f32x2 version) ----------------
__global__ __launch_bounds__(256, 2)
void atom_kernel(const int* __restrict__ species,
                 const float* __restrict__ aW0,
                 const float* __restrict__ aW1,
                 const float* __restrict__ ab1,
                 const float* __restrict__ aW2,
                 const float* __restrict__ ab2) {
    __shared__ __align__(16) float sW1[HH * HH];
    __shared__ float sTA[SS * 65];
    __shared__ float2 sGeo[HH];
    __shared__ __align__(16) float sB1[HH];
    __shared__ float sW2[HH];
    __shared__ float sRed[256];

    const int tid = threadIdx.x;
    const int b = blockIdx.y;
    const int n = blockIdx.x * 256 + tid;

    for (int idx = tid; idx < HH * HH; idx += 256) sW1[idx] = aW1[idx];
    for (int idx = tid; idx < SS * HH; idx += 256) {
        const int s = idx >> 6, k = idx & 63;
        sTA[s * 65 + k] = g_ACbase[b * HH + k] + g_Tatom[s * HH + k];
    }
    if (tid < HH) {
        sGeo[tid] = make_float2(aW0[tid], aW0[HH + tid]);
        sB1[tid] = ab1[tid];
        sW2[tid] = aW2[tid];
    }
    __syncthreads();

    const float cx = g_cp[(b * NN + n) * 2 + 0];
    const float cy = g_cp[(b * NN + n) * 2 + 1];
    const int sp = species[b * NN + n];
    const float* ta = &sTA[sp * 65];

    float h0[HH];
#pragma unroll
    for (int k = 0; k < HH; k++) {
        const float2 g = sGeo[k];
        const float z = fmaf(cx, g.x, fmaf(cy, g.y, ta[k]));
        h0[k] = silu_f(z);
    }

    float e = ab2[0];
#pragma unroll
    for (int kc = 0; kc < HH; kc += 32) {
        u64 acc[16];
        const u64* b1p = (const u64*)&sB1[kc];
#pragma unroll
        for (int m = 0; m < 16; m++) acc[m] = b1p[m];
#pragma unroll
        for (int j = 0; j < HH; j++) {
            const u64 hj = pk2(h0[j], h0[j]);
            const ulonglong2* w = (const ulonglong2*)&sW1[j * HH + kc];
#pragma unroll
            for (int m = 0; m < 8; m++) {
                const ulonglong2 ww = w[m];
                acc[2 * m + 0] = fma2(hj, ww.x, acc[2 * m + 0]);
                acc[2 * m + 1] = fma2(hj, ww.y, acc[2 * m + 1]);
            }
        }
#pragma unroll
        for (int m = 0; m < 16; m++) {
            float z0, z1;
            upk2(acc[m], z0, z1);
            e = fmaf(silu_f(z0), sW2[kc + 2 * m + 0], e);
            e = fmaf(silu_f(z1), sW2[kc + 2 * m + 1], e);
        }
    }

    sRed[tid] = e;
    __syncthreads();
    for (int s = 128; s > 0; s >>= 1) {
        if (tid < s) sRed[tid] += sRed[tid + s];
        __syncthreads();
    }
    if (tid == 0) g_atomPart[b * 4 + blockIdx.x] = sRed[0];
}

// ---------------- pair channel: persistent warp-task HMMA ----------------
// B: fp16 hi + fp16(1024*residual) lo, merged *2^-10 (systematic err ~5e-7).
// silu via packed tanh.approx.f16x2 (half the MUFU ops). W2 dot stays f32
// (fixed-weight quantization is systematic and must not be fp16).
__global__ __launch_bounds__(128, 5)
void pair_mma_kernel(const int* __restrict__ species,
                     const float* __restrict__ ef,
                     const float* __restrict__ pW0,
                     const float* __restrict__ pW1,
                     const float* __restrict__ pb1,
                     const float* __restrict__ pW2,
                     const float* __restrict__ pb2) {
    __shared__ __align__(16) char sBh[HH * STRIDE_B];     // W1^T fp16 hi
    __shared__ __align__(16) char sBl[HH * STRIDE_B];     // residual * 1024, fp16
    __shared__ __align__(16) float sTcomb[BB * 16 * TC_STRIDE];
    __shared__ __align__(16) u64 sGx[32], sGy[32], sGz[32], sGw[32];
    __shared__ __align__(8) float sB1[HH];
    __shared__ __align__(8) float sW2[HH];
    __shared__ float2 sEF[BB];

    const int tid  = threadIdx.x;
    const int wid  = tid >> 5;
    const int lane = tid & 31;

    // ---- init: B = W1^T (rows n, cols k=j)
    for (int idx = tid; idx < HH * HH; idx += 128) {
        const int n = idx >> 6, j = idx & 63;
        const float w = pW1[j * HH + n];
        const __half wh = __float2half_rn(w);
        const float r = (w - __half2float(wh)) * LO_SCALE;
        *(__half*)(sBh + n * STRIDE_B + j * 2) = wh;
        *(__half*)(sBl + n * STRIDE_B + j * 2) = __float2half_rn(r);
    }
    for (int idx = tid; idx < BB * 16 * HH; idx += 128) {
        const int bc = idx >> 6, k = idx & 63;
        const int b = bc >> 4, c = bc & 15;
        sTcomb[bc * TC_STRIDE + k] = g_Pbase[b * HH + k]
                                   + g_Tpi[(c >> 2) * HH + k]
                                   + g_Tpj[(c & 3) * HH + k];
    }
    if (tid < 32) {   // pair-packed geometry tables
        const int k = tid * 2;
        sGx[tid] = pk2(pW0[0 * HH + k], pW0[0 * HH + k + 1]);
        sGy[tid] = pk2(pW0[1 * HH + k], pW0[1 * HH + k + 1]);
        sGz[tid] = pk2(pW0[2 * HH + k], pW0[2 * HH + k + 1]);
        sGw[tid] = pk2(pW0[3 * HH + k], pW0[3 * HH + k + 1]);
    }
    if (tid < HH) {
        sB1[tid] = pb1[tid];
        sW2[tid] = pW2[tid];
    }
    if (tid < BB) sEF[tid] = make_float2(ef[tid * 2], ef[tid * 2 + 1]);
    __syncthreads();

    // ldsm2 address pieces: row = (lane&7), k-half = ((lane>>3)&1)*16 bytes
    const uint32_t bh_u = smem_u32(sBh) + (lane & 7) * STRIDE_B + ((lane >> 3) & 1) * 16;
    const uint32_t bl_u = smem_u32(sBl) + (lane & 7) * STRIDE_B + ((lane >> 3) & 1) * 16;
    const int kc4 = (lane & 3) * 2;        // fragment k offset within 16-k step
    const float pb2v = pb2[0];

    float bacc[BB];
#pragma unroll
    for (int b = 0; b < BB; b++) bacc[b] = 0.f;

    const int nwarps = gridDim.x * 4;
    const int gw = blockIdx.x * 4 + wid;

    for (int task = gw; task < NTASKS; task += nwarps) {
        // decode: b, tri -> (ti, tj), il
        const int b = task / (NTRI * 32);
        const int tt = task - b * (NTRI * 32);
        const int tri = tt >> 5, il = tt & 31;
        int rem = tri, ti = 0;
        while (rem >= NT - ti) { rem -= (NT - ti); ti++; }
        const int tj = ti + rem;
        if (ti == tj && il == 31) continue;   // fully-masked row

        const int gi = ti * NT + il;
        const float2 ci = *(const float2*)&g_cp[(b * NN + gi) * 2];
        const int si = species[b * NN + gi];
        const float2 EF = sEF[b];

        // ---- A fragments for ALL 4 K-steps, computed up front (32 regs)
        uint32_t ahi[4][2][4];
        {
            u64 rx2[4], ry2[4], dd2[4], ee2[4];
            int tcoff[4];
#pragma unroll
            for (int m = 0; m < 4; m++) {
                const int gj = tj * NT + (lane >> 2) + 8 * m;
                const float2 cj = *(const float2*)&g_cp[(b * NN + gj) * 2];
                const int sj = species[b * NN + gj];
                const float x = ci.x - cj.x, y = ci.y - cj.y;
                const float d = sqrtf(x * x + y * y);
                const float dm = fmaxf(d, 1e-12f);
                const float edu = __fdividef(fmaf(EF.x, x, EF.y * y), dm);
                rx2[m] = pk2(x, x); ry2[m] = pk2(y, y);
                dd2[m] = pk2(d, d); ee2[m] = pk2(edu, edu);
                tcoff[m] = (b * 16 + si * 4 + sj) * TC_STRIDE;
            }
#pragma unroll
            for (int ks = 0; ks < 4; ks++) {
                const int p0 = ks * 8 + (lane & 3);
                const u64 gx0 = sGx[p0],     gy0 = sGy[p0];
                const u64 gz0 = sGz[p0],     gw0 = sGw[p0];
                const u64 gx1 = sGx[p0 + 4], gy1 = sGy[p0 + 4];
                const u64 gz1 = sGz[p0 + 4], gw1 = sGw[p0 + 4];
                const int kb = ks * 16 + kc4;
#pragma unroll
                for (int m = 0; m < 4; m++) {
                    const float* tc = &sTcomb[tcoff[m]];
                    u64 z01 = *(const u64*)(tc + kb);
                    z01 = fma2(rx2[m], gx0, z01); z01 = fma2(ry2[m], gy0, z01);
                    z01 = fma2(dd2[m], gz0, z01); z01 = fma2(ee2[m], gw0, z01);
                    u64 z89 = *(const u64*)(tc + kb + 8);
                    z89 = fma2(rx2[m], gx1, z89); z89 = fma2(ry2[m], gy1, z89);
                    z89 = fma2(dd2[m], gz1, z89); z89 = fma2(ee2[m], gw1, z89);
                    float z0, z1, z8, z9;
                    upk2(z01, z0, z1); upk2(z89, z8, z9);
                    const int mt = m >> 1, sl = m & 1;
                    ahi[ks][mt][0 + sl] = silu_h2(packh2(z1, z0));
                    ahi[ks][mt][2 + sl] = silu_h2(packh2(z9, z8));
                }
            }
        }

        // ---- n-loop: 8 columns per step, transient accumulators + epilogue
        float s[4] = {0.f, 0.f, 0.f, 0.f};
#pragma unroll
        for (int ns = 0; ns < 8; ns++) {
            const float2 b1 = *(const float2*)&sB1[ns * 8 + kc4];
            float aH[2][4], aL[2][4];
#pragma unroll
            for (int mt = 0; mt < 2; mt++) {
                aH[mt][0] = b1.x; aH[mt][1] = b1.y;
                aH[mt][2] = b1.x; aH[mt][3] = b1.y;
                aL[mt][0] = 0.f; aL[mt][1] = 0.f;
                aL[mt][2] = 0.f; aL[mt][3] = 0.f;
            }
#pragma unroll
            for (int ks = 0; ks < 4; ks++) {
                const uint32_t off = ns * 8 * STRIDE_B + ks * 32;
                uint32_t rh[2], rl[2];
                ldsm2(rh, bh_u + off);
                ldsm2(rl, bl_u + off);
#pragma unroll
                for (int mt = 0; mt < 2; mt++) {
                    mma_f16s(aH[mt], ahi[ks][mt], rh[0], rh[1]);
                    mma_f16s(aL[mt], ahi[ks][mt], rl[0], rl[1]);
                }
            }
            const float2 w2 = *(const float2*)&sW2[ns * 8 + kc4];
#pragma unroll
            for (int mt = 0; mt < 2; mt++) {
                const float z0 = fmaf(aL[mt][0], LO_INV, aH[mt][0]);
                const float z1 = fmaf(aL[mt][1], LO_INV, aH[mt][1]);
                const float z2 = fmaf(aL[mt][2], LO_INV, aH[mt][2]);
                const float z3 = fmaf(aL[mt][3], LO_INV, aH[mt][3]);
                const uint32_t ha = silu_h2(packh2(z1, z0));
                const uint32_t hb = silu_h2(packh2(z3, z2));
                float f0, f1, f2, f3;
                unpkh2(ha, f0, f1);
                unpkh2(hb, f2, f3);
                s[mt * 2 + 0] = fmaf(f0, w2.x, s[mt * 2 + 0]);
                s[mt * 2 + 0] = fmaf(f1, w2.y, s[mt * 2 + 0]);
                s[mt * 2 + 1] = fmaf(f2, w2.x, s[mt * 2 + 1]);
                s[mt * 2 + 1] = fmaf(f3, w2.y, s[mt * 2 + 1]);
            }
        }

        // ---- mask + reduce
        float v = 0.f;
        int cnt = 0;
#pragma unroll
        for (int m = 0; m < 4; m++) {
            const bool mk = gi < (tj * NT + (lane >> 2) + 8 * m);
            v += mk ? s[m] : 0.f;
            cnt += (int)mk;
        }
        v += __shfl_xor_sync(0xFFFFFFFFu, v, 1);
        v += __shfl_xor_sync(0xFFFFFFFFu, v, 2);
        v = ((lane & 3) == 0) ? fmaf(pb2v, (float)cnt, v) : 0.f;
        v += __shfl_xor_sync(0xFFFFFFFFu, v, 4);
        v += __shfl_xor_sync(0xFFFFFFFFu, v, 8);
        v += __shfl_xor_sync(0xFFFFFFFFu, v, 16);
        if (lane == 0) bacc[b] += v;
    }

    if (lane == 0) {
#pragma unroll
        for (int b = 0; b < BB; b++) g_pairW[b * MAXW + gw] = bacc[b];
    }
}

// ---------------- deterministic parallel finalize ----------------
__global__ void finalize_kernel(float* __restrict__ out) {
    __shared__ float red[1024];
    const int tid = threadIdx.x;
    const int b = tid >> 8, lane = tid & 255;
    float s = 0.f;
    for (int i = lane; i < MAXW; i += 256) s += g_pairW[b * MAXW + i];
    if (lane < 4) s += g_atomPart[b * 4 + lane];
    red[tid] = s;
    __syncthreads();
    for (int st = 128; st > 0; st >>= 1) {
        if (lane < st) red[tid] += red[tid + st];
        __syncthreads();
    }
    if (lane == 0) out[b] = red[tid];
}

// ---------------- launch ----------------
extern "C" void kernel_launch(void* const* d_in, const int* in_sizes, int n_in,
                              void* d_out, int out_size) {
    const float* positions = (const float*)d_in[0];
    const int*   species   = (const int*)d_in[1];
    const float* efield    = (const float*)d_in[2];
    const float* embed     = (const float*)d_in[3];
    const float* aW0 = (const float*)d_in[4];
    const float* ab0 = (const float*)d_in[5];
    const float* aW1 = (const float*)d_in[6];
    const float* ab1 = (const float*)d_in[7];
    const float* aW2 = (const float*)d_in[8];
    const float* ab2 = (const float*)d_in[9];
    const float* pW0 = (const float*)d_in[10];
    const float* pb0 = (const float*)d_in[11];
    const float* pW1 = (const float*)d_in[12];
    const float* pb1 = (const float*)d_in[13];
    const float* pW2 = (const float*)d_in[14];
    const float* pb2 = (const float*)d_in[15];
    float* out = (float*)d_out;

    int sms = 148;
    cudaDeviceGetAttribute(&sms, cudaDevAttrMultiProcessorCount, 0);
    int grid_pair = 5 * sms;
    if (grid_pair > MAX_CTAS) grid_pair = MAX_CTAS;

    prep_kernel<<<BB, 256>>>(positions, efield, embed, aW0, ab0, pW0, pb0);
    atom_kernel<<<dim3(4, BB), 256>>>(species, aW0, aW1, ab1, aW2, ab2);
    pair_mma_kernel<<<grid_pair, 128>>>(species, efield, pW0, pW1, pb1, pW2, pb2);
    finalize_kernel<<<1, 1024>>>(out);
}